// round 3
// baseline (speedup 1.0000x reference)
#include <cuda_runtime.h>
#include <math.h>

#define SEQ   4096
#define LW    24
#define EMBD  300
#define CHOUT 25
#define CHE   25
#define HIDN  512
#define INPD  325      // EMB + CH_OUT
#define EMBS  328      // padded stride for 16B alignment
#define NTAG  11
#define STARTT 9
#define STOPT  10
#define NEGV  -10000.0f
#define NGATE 2048     // 4*HIDN
#define SENT  0x7FC00ABCu   // NaN payload sentinel: h in (-1,1) can never be NaN

typedef unsigned long long u64;

// ---------------- static device scratch (no allocs allowed) ----------------
__device__ float g_emb[SEQ * EMBS];           // 5.4 MB  [t][k]
__device__ float g_G[2][SEQ * NGATE];         // 64 MB   Wih@x + bih + bhh
__device__ float g_h[2][SEQ * HIDN];          // 16 MB   hidden states (sentinel-poisoned)
__device__ float g_feats[SEQ * 16];           // padded [t][tag]

// ---------------- helpers ----------------
__device__ __forceinline__ float4 ld_rlx4(const float4* p) {
    float4 v;
    asm volatile("ld.relaxed.gpu.global.v4.f32 {%0,%1,%2,%3}, [%4];"
                 : "=f"(v.x), "=f"(v.y), "=f"(v.z), "=f"(v.w) : "l"(p));
    return v;
}
__device__ __forceinline__ void st_rlx(float* p, float v) {
    asm volatile("st.relaxed.gpu.global.f32 [%0], %1;" :: "l"(p), "f"(v));
}
__device__ __forceinline__ u64 fma2(u64 a, u64 b, u64 c) {
    u64 d;
    asm("fma.rn.f32x2 %0, %1, %2, %3;" : "=l"(d) : "l"(a), "l"(b), "l"(c));
    return d;
}
__device__ __forceinline__ u64 add2(u64 a, u64 b) {
    u64 d;
    asm("add.rn.f32x2 %0, %1, %2;" : "=l"(d) : "l"(a), "l"(b));
    return d;
}
__device__ __forceinline__ void upk2(u64 v, float& lo, float& hi) {
    asm("mov.b64 {%0,%1}, %2;" : "=f"(lo), "=f"(hi) : "l"(v));
}
__device__ __forceinline__ float sigf(float x) {
    return __fdividef(1.0f, 1.0f + __expf(-x));
}
__device__ __forceinline__ float tanh_fast(float x) {
    return __fdividef(2.0f, 1.0f + __expf(-2.0f * x)) - 1.0f;
}

// ---------------- poison hidden-state buffer (data-as-flag protocol) --------
__global__ void poison_kernel() {
    int i = blockIdx.x * blockDim.x + threadIdx.x;   // 1M float4 = 16 MB
    float s = __uint_as_float(SENT);
    ((float4*)&g_h[0][0])[i] = make_float4(s, s, s, s);
}

// ---------------- char CNN + word-embedding gather --------------------------
__global__ void embed_kernel(const int* __restrict__ sentence,
                             const int* __restrict__ chars,
                             const float* __restrict__ word_emb,
                             const float* __restrict__ char_emb,
                             const float* __restrict__ conv_w,
                             const float* __restrict__ conv_b) {
    int s = blockIdx.x;
    int tid = threadIdx.x;
    __shared__ float ce[LW][CHE];
    __shared__ float co[CHOUT][26];
    __shared__ int   cidx[LW];

    if (tid < LW) cidx[tid] = chars[s * LW + tid];
    __syncthreads();
    for (int idx = tid; idx < LW * CHE; idx += blockDim.x) {
        int r = idx / CHE, e = idx % CHE;
        ce[r][e] = char_emb[cidx[r] * CHE + e];
    }
    __syncthreads();
    for (int idx = tid; idx < CHOUT * 26; idx += blockDim.x) {
        int o = idx / 26, p = idx % 26;
        float sum = 0.0f;
        #pragma unroll
        for (int kh = 0; kh < 3; kh++) {
            int r = p - 2 + kh;
            if (r >= 0 && r < LW) {
                const float* w = conv_w + (o * 3 + kh) * CHE;
                float ss = 0.0f;
                #pragma unroll
                for (int e = 0; e < CHE; e++) ss += ce[r][e] * w[e];
                sum += ss;
            }
        }
        co[o][p] = sum;
    }
    __syncthreads();
    if (tid < CHOUT) {
        float m = -3.4e38f;
        #pragma unroll
        for (int p = 0; p < 26; p++) m = fmaxf(m, co[tid][p]);
        g_emb[s * EMBS + EMBD + tid] = m + conv_b[tid];
    }
    int wi = sentence[s];
    const float4* src = (const float4*)(word_emb + (size_t)wi * EMBD);
    float4* dst = (float4*)(g_emb + (size_t)s * EMBS);
    for (int i = tid; i < EMBD / 4; i += blockDim.x) dst[i] = src[i];
}

// ---------------- G = emb @ Wih^T + (bih + bhh) -----------------------------
__global__ __launch_bounds__(256) void gemm_kernel(
    const float* __restrict__ Wihf, const float* __restrict__ Wihb,
    const float* __restrict__ bihf, const float* __restrict__ bhhf,
    const float* __restrict__ bihb, const float* __restrict__ bhhb) {
    int dir = blockIdx.z;
    const float* Wih = dir ? Wihb : Wihf;
    const float* bih = dir ? bihb : bihf;
    const float* bhh = dir ? bhhb : bhhf;
    int bm = blockIdx.y * 64;
    int bn = blockIdx.x * 64;
    int tid = threadIdx.x;
    int tx = tid & 15, ty = tid >> 4;

    __shared__ __align__(16) float As[8][68];
    __shared__ __align__(16) float Bs[8][68];

    float acc[4][4] = {};
    for (int k0 = 0; k0 < INPD; k0 += 8) {
        #pragma unroll
        for (int q = 0; q < 2; q++) {
            int idx = tid + q * 256;
            int kk = idx & 7, m = idx >> 3;
            int k = k0 + kk;
            As[kk][m] = (k < INPD) ? g_emb[(size_t)(bm + m) * EMBS + k] : 0.0f;
            Bs[kk][m] = (k < INPD) ? Wih[(size_t)(bn + m) * INPD + k] : 0.0f;
        }
        __syncthreads();
        #pragma unroll
        for (int kk = 0; kk < 8; kk++) {
            float4 a = *(const float4*)&As[kk][ty * 4];
            float4 b = *(const float4*)&Bs[kk][tx * 4];
            float av[4] = {a.x, a.y, a.z, a.w};
            float bv[4] = {b.x, b.y, b.z, b.w};
            #pragma unroll
            for (int i = 0; i < 4; i++)
                #pragma unroll
                for (int j = 0; j < 4; j++) acc[i][j] += av[i] * bv[j];
        }
        __syncthreads();
    }
    float* Gp = g_G[dir];
    #pragma unroll
    for (int i = 0; i < 4; i++) {
        int t = bm + ty * 4 + i;
        #pragma unroll
        for (int j = 0; j < 4; j++) {
            int n = bn + tx * 4 + j;
            Gp[(size_t)t * NGATE + n] = acc[i][j] + bih[n] + bhh[n];
        }
    }
}

// ---------------- persistent BiLSTM recurrence -------------------------------
// 128 blocks (64/dir), 256 threads = 8 warps. Warp w owns output h[j], j =
// b*8+w. Lane l covers columns {q*128 + l*4 .. +4} for q=0..3, shared across
// all 4 gates (4x less LDS traffic). f32x2 packed FMAs. In-warp reduce; gates
// on lanes 0-3 in parallel; lane 0 owns cstate and stores h. Data-as-flag
// sync (NaN sentinel), no atomics/fences.
__global__ __launch_bounds__(256, 1) void lstm_kernel(
    const float* __restrict__ Whhf, const float* __restrict__ Whhb) {
    int dir = blockIdx.x >> 6;
    int b = blockIdx.x & 63;
    int tid = threadIdx.x;
    int w = tid >> 5;       // warp -> local j
    int l = tid & 31;       // lane -> column group
    int j = b * 8 + w;      // global h index owned by this warp
    const float* Whh = dir ? Whhb : Whhf;

    // weights: [gate][q] 16B chunks -> 64 regs, resident whole sequence
    ulonglong2 wgt[4][4];
    #pragma unroll
    for (int g = 0; g < 4; g++)
        #pragma unroll
        for (int q = 0; q < 4; q++)
            wgt[g][q] = *(const ulonglong2*)(Whh + (size_t)(g * HIDN + j) * HIDN
                                             + q * 128 + l * 4);

    __shared__ float4 hs[128];    // staged h_prev (linear: hs[i] = h[4i..4i+3])
    const ulonglong2* hsu = (const ulonglong2*)hs;

    const float* Gp = g_G[dir];
    float* hp = g_h[dir];
    float cstate = 0.0f;

    // prefetch G for step 0 (lane k of each warp holds gate k's input proj)
    int t0 = dir ? (SEQ - 1) : 0;
    float gnext = 0.0f;
    if (l < 4) gnext = Gp[(size_t)t0 * NGATE + l * HIDN + j];

    for (int s = 0; s < SEQ; s++) {
        int t = dir ? (SEQ - 1 - s) : s;
        float gcur = gnext;
        if (l < 4 && s + 1 < SEQ) {
            int tn = dir ? (t - 1) : (t + 1);
            gnext = Gp[(size_t)tn * NGATE + l * HIDN + j];
        }

        if (s > 0) {
            int pt = dir ? (t + 1) : (t - 1);
            if (tid < 128) {
                const float4* src = (const float4*)(hp + (size_t)pt * HIDN) + tid;
                float4 v;
                do {
                    v = ld_rlx4(src);
                } while (__float_as_uint(v.x) == SENT || __float_as_uint(v.y) == SENT ||
                         __float_as_uint(v.z) == SENT || __float_as_uint(v.w) == SENT);
                hs[tid] = v;
            }
        } else {
            if (tid < 128) hs[tid] = make_float4(0.f, 0.f, 0.f, 0.f);
        }
        __syncthreads();

        // conflict-free: lanes 0..31 read consecutive 16B chunks per q
        ulonglong2 h0 = hsu[l];
        ulonglong2 h1 = hsu[32 + l];
        ulonglong2 h2 = hsu[64 + l];
        ulonglong2 h3 = hsu[96 + l];

        float sg[4];
        #pragma unroll
        for (int g = 0; g < 4; g++) {
            u64 a0 = fma2(wgt[g][0].x, h0.x, 0ULL);
            u64 a1 = fma2(wgt[g][0].y, h0.y, 0ULL);
            a0 = fma2(wgt[g][1].x, h1.x, a0);
            a1 = fma2(wgt[g][1].y, h1.y, a1);
            a0 = fma2(wgt[g][2].x, h2.x, a0);
            a1 = fma2(wgt[g][2].y, h2.y, a1);
            a0 = fma2(wgt[g][3].x, h3.x, a0);
            a1 = fma2(wgt[g][3].y, h3.y, a1);
            float lo, hi;
            upk2(add2(a0, a1), lo, hi);
            sg[g] = lo + hi;
        }
        // full warp reduce on 4 independent sums
        #pragma unroll
        for (int g = 0; g < 4; g++) {
            float v = sg[g];
            v += __shfl_xor_sync(0xffffffffu, v, 16);
            v += __shfl_xor_sync(0xffffffffu, v, 8);
            v += __shfl_xor_sync(0xffffffffu, v, 4);
            v += __shfl_xor_sync(0xffffffffu, v, 2);
            v += __shfl_xor_sync(0xffffffffu, v, 1);
            sg[g] = v;
        }
        // gate nonlinearities in parallel on lanes 0..3
        float x = sg[l & 3] + gcur;
        float v = (l == 2) ? tanh_fast(x) : sigf(x);
        float vf = __shfl_sync(0xffffffffu, v, 1);
        float vg = __shfl_sync(0xffffffffu, v, 2);
        float vo = __shfl_sync(0xffffffffu, v, 3);
        if (l == 0) {
            cstate = vf * cstate + v * vg;
            float h = vo * tanh_fast(cstate);
            st_rlx(hp + (size_t)t * HIDN + j, h);
        }
        // no trailing barrier: a successful poll at s+1 implies every warp of
        // every producing block (incl. this one) finished reading hs at s.
    }
}

// ---------------- feats = [h_f ; h_b] @ h2t_w^T + h2t_b ---------------------
__global__ void feats_kernel(const float* __restrict__ h2t_w,
                             const float* __restrict__ h2t_b) {
    int t = blockIdx.x;
    int tid = threadIdx.x;
    int w = tid >> 5, lane = tid & 31;
    const float* hf = g_h[0] + (size_t)t * HIDN;
    const float* hb = g_h[1] + (size_t)t * HIDN;
    const float* wr = h2t_w + w * (2 * HIDN);
    float acc = 0.0f;
    #pragma unroll
    for (int it = 0; it < 16; it++) {
        int k = lane + it * 32;
        acc += wr[k] * hf[k];
        acc += wr[512 + k] * hb[k];
    }
    #pragma unroll
    for (int o = 16; o > 0; o >>= 1) acc += __shfl_down_sync(0xffffffffu, acc, o);
    if (lane == 0) g_feats[t * 16 + w] = acc + h2t_b[w];
}

// ---------------- Viterbi + backtrack ---------------------------------------
// 128 threads: chunks of 32 timesteps staged into SMEM by one coalesced load,
// then warp 0 runs the recurrence with fv held in registers (shfl all-to-all,
// no per-step syncs). Backpointers stay in SMEM for the backtrack.
__global__ void viterbi_kernel(const float* __restrict__ trans,
                               float* __restrict__ out, int out_size) {
    __shared__ unsigned char bp[SEQ][NTAG];   // 45 KB
    __shared__ float fbuf[32 * 16];           // 2 KB chunk of feats
    __shared__ float fvv[NTAG];
    int tid = threadIdx.x;
    int w = tid >> 5, lane = tid & 31;

    float trow[NTAG];
    float fv = NEGV;
    if (w == 0) {
        #pragma unroll
        for (int jj = 0; jj < NTAG; jj++)
            trow[jj] = (lane < NTAG) ? trans[lane * NTAG + jj] : NEGV;
        if (lane == STARTT) fv = 0.0f;
    }

    for (int c = 0; c < SEQ / 32; c++) {
        ((float4*)fbuf)[tid] = ((const float4*)(g_feats + c * 32 * 16))[tid];
        __syncthreads();
        if (w == 0) {
            #pragma unroll 4
            for (int tt = 0; tt < 32; tt++) {
                int t = c * 32 + tt;
                float featv = (lane < NTAG) ? fbuf[tt * 16 + lane] : 0.0f;
                float best = -3.4e38f; int arg = 0;
                #pragma unroll
                for (int jj = 0; jj < NTAG; jj++) {
                    float vj = __shfl_sync(0xffffffffu, fv, jj) + trow[jj];
                    if (vj > best) { best = vj; arg = jj; }
                }
                fv = best + featv;
                if (lane < NTAG) bp[t][lane] = (unsigned char)arg;
            }
        }
        __syncthreads();
    }

    if (w == 0 && lane < NTAG) fvv[lane] = fv;
    __syncthreads();

    if (tid == 0) {
        float bestv = -3.4e38f; int bi = 0;
        #pragma unroll
        for (int i = 0; i < NTAG; i++) {
            float v = fvv[i] + trans[STOPT * NTAG + i];
            if (i == STARTT || i == STOPT) v = NEGV;
            if (v > bestv) { bestv = v; bi = i; }
        }
        if (out_size > 0) out[0] = bestv;
        int tag = bi;
        for (int t = SEQ - 1; t >= 0; t--) {
            if (1 + t < out_size) out[1 + t] = (float)tag;
            tag = bp[t][tag];
        }
    }
}

// ---------------- launch --------------------------------------------------
extern "C" void kernel_launch(void* const* d_in, const int* in_sizes, int n_in,
                              void* d_out, int out_size) {
    const int*   sentence = (const int*)d_in[0];
    const int*   chars    = (const int*)d_in[1];
    const float* word_emb = (const float*)d_in[4];
    const float* char_emb = (const float*)d_in[5];
    const float* conv_w   = (const float*)d_in[6];
    const float* conv_b   = (const float*)d_in[7];
    const float* Wih_f    = (const float*)d_in[8];
    const float* Whh_f    = (const float*)d_in[9];
    const float* bih_f    = (const float*)d_in[10];
    const float* bhh_f    = (const float*)d_in[11];
    const float* Wih_b    = (const float*)d_in[12];
    const float* Whh_b    = (const float*)d_in[13];
    const float* bih_b    = (const float*)d_in[14];
    const float* bhh_b    = (const float*)d_in[15];
    const float* h2t_w    = (const float*)d_in[16];
    const float* h2t_b    = (const float*)d_in[17];
    const float* trans    = (const float*)d_in[18];
    float* out = (float*)d_out;

    poison_kernel<<<4096, 256>>>();
    embed_kernel<<<SEQ, 128>>>(sentence, chars, word_emb, char_emb, conv_w, conv_b);
    dim3 gg(NGATE / 64, SEQ / 64, 2);
    gemm_kernel<<<gg, 256>>>(Wih_f, Wih_b, bih_f, bhh_f, bih_b, bhh_b);
    lstm_kernel<<<128, 256>>>(Whh_f, Whh_b);
    feats_kernel<<<SEQ, 352>>>(h2t_w, h2t_b);
    viterbi_kernel<<<1, 128>>>(trans, out, out_size);
}